// round 16
// baseline (speedup 1.0000x reference)
#include <cuda_runtime.h>
#include <cuda_bf16.h>
#include <cstdint>
#include <math.h>

#define BB 32
#define SS 256
#define HH 512
#define EE 512
#define VV 32000
#define LL 64
#define SOS_TOK 1
#define G3 1536
#define MALL (LL * BB)          // 2048
#define NB 64                   // persistent blocks
#define KC 1536                 // logical split K (3*512)
#define LDK 1024                // stored row width [hi|lo]
#define LSM_SMEM (VV * 4)       // 128000 bytes

// recur dynamic smem: sW1(512*32) | sA(64*33) | sW3(512*24)
#define RS_W1 0
#define RS_A  (512 * 32)
#define RS_W3 (512 * 32 + 64 * 33)
#define RECUR_SMEM ((512 * 32 + 64 * 33 + 512 * 24) * 4)

// ---------------- scratch (device globals) --------------------------------
__device__ float g_h[BB * HH];
__device__ float g_hall[MALL * HH];          // (t,b,H)
__device__ float g_Uk[BB * SS * HH];         // 16.8MB
__device__ float g_emball[MALL * HH];        // embedded tokens (t,b,H)
__device__ float g_gipre[MALL * G3];         // emb part of gi + b_ih
__device__ float g_qgh[BB * 2048];           // per-step [q | gh]
__device__ float g_scores[BB * SS];
__device__ float g_ctx[BB * HH];
__device__ unsigned int g_barcnt = 0;
__device__ unsigned int g_bargen = 0;

// split bf16 operands, stored [hi | lo], row width LDK=1024
__device__ __nv_bfloat16 g_encA[BB * SS * LDK];
__device__ __nv_bfloat16 g_UaB[HH * LDK];
__device__ __nv_bfloat16 g_embA[MALL * LDK];
__device__ __nv_bfloat16 g_WihB[G3 * LDK];
__device__ __nv_bfloat16 g_haA[MALL * LDK];
__device__ __nv_bfloat16 g_WoutB[(size_t)VV * LDK];

// ---------------- math helpers --------------------------------------------
__device__ __forceinline__ float ftanh_fast(float x) {
    float r;
    asm("tanh.approx.f32 %0, %1;" : "=f"(r) : "f"(x));
    return r;
}
__device__ __forceinline__ float ftanh(float x) {
    float e = __expf(2.0f * x);
    return 1.0f - __fdividef(2.0f, e + 1.0f);
}
__device__ __forceinline__ float fsig(float x) {
    return __fdividef(1.0f, 1.0f + __expf(-x));
}

__device__ __forceinline__ uint32_t smem_u32(const void* p) {
    uint32_t a;
    asm("{ .reg .u64 t; cvta.to.shared.u64 t, %1; cvt.u32.u64 %0, t; }" : "=r"(a) : "l"(p));
    return a;
}
__device__ __forceinline__ void ldsm4(uint32_t (&r)[4], uint32_t addr) {
    asm volatile("ldmatrix.sync.aligned.m8n8.x4.shared.b16 {%0,%1,%2,%3}, [%4];"
                 : "=r"(r[0]), "=r"(r[1]), "=r"(r[2]), "=r"(r[3]) : "r"(addr));
}
__device__ __forceinline__ void mma16816(float (&d)[4], const uint32_t (&a)[4],
                                         const uint32_t* b) {
    asm volatile(
        "mma.sync.aligned.m16n8k16.row.col.f32.bf16.bf16.f32 "
        "{%0,%1,%2,%3}, {%4,%5,%6,%7}, {%8,%9}, {%0,%1,%2,%3};"
        : "+f"(d[0]), "+f"(d[1]), "+f"(d[2]), "+f"(d[3])
        : "r"(a[0]), "r"(a[1]), "r"(a[2]), "r"(a[3]), "r"(b[0]), "r"(b[1]));
}
#define CP16(dst, src) \
    asm volatile("cp.async.cg.shared.global [%0], [%1], 16;" :: "r"(dst), "l"(src))
#define CPCOMMIT() asm volatile("cp.async.commit_group;" ::: "memory")
#define CPWAIT1() asm volatile("cp.async.wait_group 1;" ::: "memory")
#define CPWAIT0() asm volatile("cp.async.wait_group 0;" ::: "memory")

// ================= split conversion: fp32 -> [hi|lo] =======================
__device__ __forceinline__ uint32_t pkbf(__nv_bfloat16 a, __nv_bfloat16 b) {
    return (uint32_t)__bfloat16_as_ushort(a) | ((uint32_t)__bfloat16_as_ushort(b) << 16);
}
__device__ __forceinline__ void conv_body(const float* __restrict__ src, int srcLd,
                                          __nv_bfloat16* __restrict__ dst, int i) {
    int r = i >> 7, c4 = (i & 127) * 4;
    float4 v = *reinterpret_cast<const float4*>(src + (size_t)r * srcLd + c4);
    __nv_bfloat16 h0 = __float2bfloat16(v.x), h1 = __float2bfloat16(v.y);
    __nv_bfloat16 h2 = __float2bfloat16(v.z), h3 = __float2bfloat16(v.w);
    __nv_bfloat16 l0 = __float2bfloat16(v.x - __bfloat162float(h0));
    __nv_bfloat16 l1 = __float2bfloat16(v.y - __bfloat162float(h1));
    __nv_bfloat16 l2 = __float2bfloat16(v.z - __bfloat162float(h2));
    __nv_bfloat16 l3 = __float2bfloat16(v.w - __bfloat162float(h3));
    uint2 hw = make_uint2(pkbf(h0, h1), pkbf(h2, h3));
    uint2 lw = make_uint2(pkbf(l0, l1), pkbf(l2, l3));
    __nv_bfloat16* drow = dst + (size_t)r * LDK;
    *reinterpret_cast<uint2*>(drow + c4) = hw;
    *reinterpret_cast<uint2*>(drow + 512 + c4) = lw;
}
__global__ void __launch_bounds__(256)
convcat(const float* __restrict__ src, int srcLd,
        __nv_bfloat16* __restrict__ dst, int R) {
    int i = blockIdx.x * 256 + threadIdx.x;
    if (i >= R * 128) return;
    conv_body(src, srcLd, dst, i);
}
// fused pre-recur conversions + h0 GEMM (blocks 6144..6151)
__global__ void __launch_bounds__(256)
convcat4x(const float* __restrict__ enc, const float* __restrict__ Ua,
          const float* __restrict__ Wih,
          const float* __restrict__ ehid, const float* __restrict__ W_ht,
          const float* __restrict__ b_ht) {
    int bx = blockIdx.x;
    if (bx < 4096) {
        conv_body(enc, EE, g_encA, bx * 256 + threadIdx.x);
    } else if (bx < 4352) {
        conv_body(Ua, EE, g_UaB, (bx - 4096) * 256 + threadIdx.x);
    } else if (bx < 5376) {
        conv_body(g_emball, HH, g_embA, (bx - 4352) * 256 + threadIdx.x);
    } else if (bx < 6144) {
        conv_body(Wih, 1024, g_WihB, (bx - 5376) * 256 + threadIdx.x);
    } else {
        __shared__ float As[32][33];
        __shared__ float Bs[32][65];
        const int tid = threadIdx.x;
        const int act = (tid < 128);
        const int n0 = (bx - 6144) * 64;
        const int la_m = tid >> 2, la_k = (tid & 3) << 2;
        const int lb_n = tid >> 1, lb_k = (tid & 1) << 2;
        const int tm = tid >> 4, tn = tid & 15;
        float acc[4][4];
#pragma unroll
        for (int i = 0; i < 4; i++)
#pragma unroll
            for (int j = 0; j < 4; j++) acc[i][j] = 0.f;
        const float* Arow = ehid + (size_t)la_m * EE;
        const float* Brow = W_ht + (size_t)(n0 + lb_n) * EE;
        for (int k0 = 0; k0 < EE; k0 += 32) {
            if (act) {
                float4 av0 = *reinterpret_cast<const float4*>(Arow + k0 + la_k);
                float4 av1 = *reinterpret_cast<const float4*>(Arow + k0 + la_k + 16);
                As[la_k + 0][la_m] = av0.x;  As[la_k + 1][la_m] = av0.y;
                As[la_k + 2][la_m] = av0.z;  As[la_k + 3][la_m] = av0.w;
                As[la_k + 16][la_m] = av1.x; As[la_k + 17][la_m] = av1.y;
                As[la_k + 18][la_m] = av1.z; As[la_k + 19][la_m] = av1.w;
                float4 bv0 = *reinterpret_cast<const float4*>(Brow + k0 + lb_k);
                float4 bv1 = *reinterpret_cast<const float4*>(Brow + k0 + lb_k + 8);
                float4 bv2 = *reinterpret_cast<const float4*>(Brow + k0 + lb_k + 16);
                float4 bv3 = *reinterpret_cast<const float4*>(Brow + k0 + lb_k + 24);
                Bs[lb_k + 0][lb_n] = bv0.x;  Bs[lb_k + 1][lb_n] = bv0.y;
                Bs[lb_k + 2][lb_n] = bv0.z;  Bs[lb_k + 3][lb_n] = bv0.w;
                Bs[lb_k + 8][lb_n] = bv1.x;  Bs[lb_k + 9][lb_n] = bv1.y;
                Bs[lb_k + 10][lb_n] = bv1.z; Bs[lb_k + 11][lb_n] = bv1.w;
                Bs[lb_k + 16][lb_n] = bv2.x; Bs[lb_k + 17][lb_n] = bv2.y;
                Bs[lb_k + 18][lb_n] = bv2.z; Bs[lb_k + 19][lb_n] = bv2.w;
                Bs[lb_k + 24][lb_n] = bv3.x; Bs[lb_k + 25][lb_n] = bv3.y;
                Bs[lb_k + 26][lb_n] = bv3.z; Bs[lb_k + 27][lb_n] = bv3.w;
            }
            __syncthreads();
            if (act) {
#pragma unroll
                for (int kk = 0; kk < 32; kk++) {
                    float a0 = As[kk][tm * 4 + 0], a1 = As[kk][tm * 4 + 1];
                    float a2 = As[kk][tm * 4 + 2], a3 = As[kk][tm * 4 + 3];
                    float b0 = Bs[kk][tn * 4 + 0], b1 = Bs[kk][tn * 4 + 1];
                    float b2 = Bs[kk][tn * 4 + 2], b3 = Bs[kk][tn * 4 + 3];
                    acc[0][0] += a0 * b0; acc[0][1] += a0 * b1; acc[0][2] += a0 * b2; acc[0][3] += a0 * b3;
                    acc[1][0] += a1 * b0; acc[1][1] += a1 * b1; acc[1][2] += a1 * b2; acc[1][3] += a1 * b3;
                    acc[2][0] += a2 * b0; acc[2][1] += a2 * b1; acc[2][2] += a2 * b2; acc[2][3] += a2 * b3;
                    acc[3][0] += a3 * b0; acc[3][1] += a3 * b1; acc[3][2] += a3 * b2; acc[3][3] += a3 * b3;
                }
            }
            __syncthreads();
        }
        if (act) {
#pragma unroll
            for (int i = 0; i < 4; i++) {
                float* crow = g_h + (size_t)(tm * 4 + i) * HH + n0 + tn * 4;
#pragma unroll
                for (int j = 0; j < 4; j++) crow[j] = acc[i][j] + b_ht[n0 + tn * 4 + j];
            }
        }
    }
}

// ================= HMMA GEMM body (dedup-remapped K) =======================
// Logical C = Acat(M,1536) @ Bcat(N,1536)^T with A=[hi|lo|hi], B=[hi|hi|lo];
// storage is [hi|lo] (LDK=1024): ktA = kt<1024?kt:kt-1024; ktB = kt<512?kt:kt-512.
__device__ __forceinline__ void mma_body(
    const __nv_bfloat16* __restrict__ A, const __nv_bfloat16* __restrict__ B,
    const float* __restrict__ bias, float* __restrict__ C, int ldC, int remap,
    int bxM, int byN) {
    __shared__ __align__(16) __nv_bfloat16 sA[2][128][40];
    __shared__ __align__(16) __nv_bfloat16 sB[2][128][40];
    const int tid = threadIdx.x;
    const int lane = tid & 31, wid = tid >> 5;
    const int warpM = wid >> 1, warpN = wid & 1;
    const int m0 = bxM * 128, n0 = byN * 128;

    float acc[2][8][4];
#pragma unroll
    for (int i = 0; i < 2; i++)
#pragma unroll
        for (int j = 0; j < 8; j++)
#pragma unroll
            for (int k = 0; k < 4; k++) acc[i][j][k] = 0.f;

    const int ldRow = tid >> 2;
    const int ldSeg = (tid & 3) * 8;

    const __nv_bfloat16* gA0 = A + (size_t)(m0 + ldRow) * LDK + ldSeg;
    const __nv_bfloat16* gA1 = gA0 + (size_t)64 * LDK;
    const __nv_bfloat16* gB0 = B + (size_t)(n0 + ldRow) * LDK + ldSeg;
    const __nv_bfloat16* gB1 = gB0 + (size_t)64 * LDK;
    uint32_t dA[2][2], dB[2][2];
#pragma unroll
    for (int st = 0; st < 2; st++) {
        dA[st][0] = smem_u32(&sA[st][ldRow][ldSeg]);
        dA[st][1] = smem_u32(&sA[st][ldRow + 64][ldSeg]);
        dB[st][0] = smem_u32(&sB[st][ldRow][ldSeg]);
        dB[st][1] = smem_u32(&sB[st][ldRow + 64][ldSeg]);
    }

    const int aRowOff = ((lane & 8) ? 8 : 0) + (lane & 7);
    const int aColOff = (lane & 16) ? 8 : 0;
    const int bRowOff = ((lane & 16) ? 8 : 0) + (lane & 7);
    const int bColOff = (lane & 8) ? 8 : 0;

    const int NK = KC / 32;   // 48

    // prefetch kt=0 (ktA=0, ktB=0)
    CP16(dA[0][0], gA0); CP16(dA[0][1], gA1);
    CP16(dB[0][0], gB0); CP16(dB[0][1], gB1);
    CPCOMMIT();

    for (int it = 0; it < NK; it++) {
        if (it + 1 < NK) {
            int st = (it + 1) & 1, kt = (it + 1) * 32;
            int ktA = (kt < 1024) ? kt : kt - 1024;
            int ktB = (kt < 512) ? kt : kt - 512;
            CP16(dA[st][0], gA0 + ktA); CP16(dA[st][1], gA1 + ktA);
            CP16(dB[st][0], gB0 + ktB); CP16(dB[st][1], gB1 + ktB);
            CPCOMMIT();
            CPWAIT1();
        } else {
            CPWAIT0();
        }
        __syncthreads();

        const int cs = it & 1;
        const uint32_t aBase = smem_u32(&sA[cs][0][0]);
        const uint32_t bBase = smem_u32(&sB[cs][0][0]);
#pragma unroll
        for (int ks = 0; ks < 2; ks++) {
            const int k0 = ks * 16;
            uint32_t a[2][4];
#pragma unroll
            for (int mi = 0; mi < 2; mi++) {
                int row = warpM * 32 + mi * 16 + aRowOff;
                int col = k0 + aColOff;
                ldsm4(a[mi], aBase + (uint32_t)(row * 80 + col * 2));
            }
            uint32_t b[4][4];
#pragma unroll
            for (int bi = 0; bi < 4; bi++) {
                int row = warpN * 64 + bi * 16 + bRowOff;
                int col = k0 + bColOff;
                ldsm4(b[bi], bBase + (uint32_t)(row * 80 + col * 2));
            }
#pragma unroll
            for (int mi = 0; mi < 2; mi++)
#pragma unroll
                for (int ni = 0; ni < 8; ni++)
                    mma16816(acc[mi][ni], a[mi], &b[ni >> 1][(ni & 1) * 2]);
        }
        __syncthreads();
    }

    const int er = lane >> 2, ec = (lane & 3) * 2;
#pragma unroll
    for (int mi = 0; mi < 2; mi++) {
#pragma unroll
        for (int half = 0; half < 2; half++) {
            int m = m0 + warpM * 32 + mi * 16 + er + half * 8;
            int row = remap ? ((m & 31) * LL + (m >> 5)) : m;
            float* cp = C + (size_t)row * ldC;
#pragma unroll
            for (int ni = 0; ni < 8; ni++) {
                int n = n0 + warpN * 64 + ni * 8 + ec;
                float2 v;
                v.x = acc[mi][ni][half * 2 + 0] + bias[n];
                v.y = acc[mi][ni][half * 2 + 1] + bias[n + 1];
                *reinterpret_cast<float2*>(cp + n) = v;
            }
        }
    }
}

__global__ void __launch_bounds__(256, 2)
mmaGemm(const __nv_bfloat16* __restrict__ A, const __nv_bfloat16* __restrict__ B,
        const float* __restrict__ bias, float* __restrict__ C, int ldC, int remap) {
    mma_body(A, B, bias, C, ldC, remap, blockIdx.x, blockIdx.y);
}
__global__ void __launch_bounds__(256, 2)
mmaPre(const float* __restrict__ bUa, const float* __restrict__ b_ih,
       float* __restrict__ Uk, float* __restrict__ gipre) {
    int id = blockIdx.x;
    if (id < 256) {
        mma_body(g_encA, g_UaB, bUa, Uk, HH, 0, id >> 2, id & 3);
    } else {
        int j = id - 256;
        mma_body(g_embA, g_WihB, b_ih, gipre, G3, 0, j & 15, j >> 4);
    }
}

// ================= embedding gather ========================================
__global__ void gather_emb(const int* __restrict__ tgt, const float* __restrict__ emb) {
    int i = blockIdx.x * 256 + threadIdx.x;
    int row = i >> 7;
    int c = i & 127;
    int tcur = row >> 5, b = row & 31;
    int tok = (tcur == 0) ? SOS_TOK : tgt[b * LL + tcur - 1];
    reinterpret_cast<float4*>(g_emball)[(size_t)row * 128 + c] =
        reinterpret_cast<const float4*>(emb + (size_t)tok * HH)[c];
}

// ================= persistent recurrence kernel (NB=64) ====================
__device__ __forceinline__ void gridbar() {
    __syncthreads();
    if (threadIdx.x == 0) {
        volatile unsigned int* genp = &g_bargen;
        unsigned int gen = *genp;
        __threadfence();
        unsigned int t = atomicAdd(&g_barcnt, 1u);
        if (t == NB - 1) {
            g_barcnt = 0;
            __threadfence();
            *genp = gen + 1;
        } else {
            while (*genp == gen) { }
        }
        __threadfence();
    }
    __syncthreads();
}

__global__ void __launch_bounds__(256)
recur(const float* __restrict__ enc,
      const float* __restrict__ Wa, const float* __restrict__ ba,
      const float* __restrict__ W_hh, const float* __restrict__ b_hh,
      const float* __restrict__ W_ih,
      const float* __restrict__ Va, const float* __restrict__ bVa,
      float* __restrict__ out_attn) {
    extern __shared__ float dsm[];
    float* sW1 = dsm + RS_W1;                 // [k][32]  (512x32)
    float* sA  = dsm + RS_A;                  // [64][33] staging / misc
    float* sW3 = dsm + RS_W3;                 // [k][3][8] (512x24)
    const int blk = blockIdx.x;               // 0..63
    const int tid = threadIdx.x;
    const int lane = tid & 31;
    const int wrp = tid >> 5;

    // ---- one-time: load resident weight slices ----------------------------
    {
        // P1 weights: 32 rows of [Wa;W_hh] starting at n0=blk*32, k-major
        int n0 = blk * 32;
        const float* Bp = (n0 < HH) ? (Wa + (size_t)n0 * HH)
                                    : (W_hh + (size_t)(n0 - HH) * HH);
        for (int idx = tid; idx < 32 * 512; idx += 256) {
            int j = idx >> 9, k = idx & 511;
            sW1[k * 32 + j] = Bp[(size_t)j * HH + k];
        }
        // P3P4 weights: 24 rows (3 gates x 8 i) of W_ih[:,512:1024]
        {
            int i0 = blk * 8;
            for (int idx = tid; idx < 24 * 512; idx += 256) {
                int row = idx >> 9, k = idx & 511;
                int gate = row >> 3, gg = row & 7;
                sW3[k * 24 + gate * 8 + gg] =
                    W_ih[(size_t)(gate * 512 + i0 + gg) * 1024 + 512 + k];
            }
        }
        __syncthreads();
    }
    float (*As)[33] = reinterpret_cast<float(*)[33]>(sA);

    for (int t = 0; t < LL; t++) {
        // ---- P1: 32 cols of [q | gh] per block (resident weights) ---------
        {
            int n0 = blk * 32;
            const float* bp = (n0 < HH) ? (ba + n0) : (b_hh + n0 - HH);
            const int m = tid & 31, g = tid >> 5;      // m=b-row, g: 4 cols
            float acc0 = 0.f, acc1 = 0.f, acc2 = 0.f, acc3 = 0.f;
            for (int kt = 0; kt < 512; kt += 64) {
                const float* ap = g_h + (size_t)m * 512 + kt + g * 8;
                float4 a0 = *reinterpret_cast<const float4*>(ap);
                float4 a1 = *reinterpret_cast<const float4*>(ap + 4);
                As[g * 8 + 0][m] = a0.x; As[g * 8 + 1][m] = a0.y;
                As[g * 8 + 2][m] = a0.z; As[g * 8 + 3][m] = a0.w;
                As[g * 8 + 4][m] = a1.x; As[g * 8 + 5][m] = a1.y;
                As[g * 8 + 6][m] = a1.z; As[g * 8 + 7][m] = a1.w;
                __syncthreads();
                const float* wrow = sW1 + (size_t)kt * 32 + g * 4;
#pragma unroll
                for (int kk = 0; kk < 64; kk++) {
                    float a = As[kk][m];
                    float4 w = *reinterpret_cast<const float4*>(wrow + kk * 32);
                    acc0 = fmaf(a, w.x, acc0);
                    acc1 = fmaf(a, w.y, acc1);
                    acc2 = fmaf(a, w.z, acc2);
                    acc3 = fmaf(a, w.w, acc3);
                }
                __syncthreads();
            }
            int j = g * 4;
            float4 o = make_float4(acc0 + bp[j], acc1 + bp[j + 1],
                                   acc2 + bp[j + 2], acc3 + bp[j + 3]);
            *reinterpret_cast<float4*>(g_qgh + (size_t)m * 2048 + n0 + j) = o;
        }
        gridbar();

        // ---- P2a: scores (tanh.approx), 64 blocks = (b, 128-s chunk) ------
        {
            int b = blk & 31;
            int s0 = (blk >> 5) * 128;
            float* sq = sA;
            float* sva = sA + 512;
            sq[tid] = g_qgh[b * 2048 + tid];
            sq[tid + 256] = g_qgh[b * 2048 + tid + 256];
            sva[tid] = Va[tid];
            sva[tid + 256] = Va[tid + 256];
            __syncthreads();
            const float4* q4 = reinterpret_cast<const float4*>(sq);
            const float4* v4 = reinterpret_cast<const float4*>(sva);
            for (int it = 0; it < 16; it++) {
                int s = s0 + wrp + 8 * it;
                const float4* u4 = reinterpret_cast<const float4*>(
                    g_Uk + ((size_t)(b * SS + s)) * HH);
                float p = 0.f;
#pragma unroll
                for (int c = 0; c < 4; c++) {
                    int k4 = lane + 32 * c;
                    float4 uv = u4[k4];
                    float4 qv = q4[k4];
                    float4 vv = v4[k4];
                    p += vv.x * ftanh_fast(qv.x + uv.x) + vv.y * ftanh_fast(qv.y + uv.y)
                       + vv.z * ftanh_fast(qv.z + uv.z) + vv.w * ftanh_fast(qv.w + uv.w);
                }
                for (int o = 16; o; o >>= 1) p += __shfl_xor_sync(0xffffffffu, p, o);
                if (lane == 0) g_scores[b * SS + s] = p + bVa[0];
            }
            __syncthreads();
        }
        gridbar();

        // ---- P2b: softmax (no max-sub) + attn out + ctx (2 blocks per b) --
        {
            int b = blk >> 1, q = blk & 1;
            float* sw = sA;
            float* red = sA + 256;
            float v = g_scores[b * SS + tid];
            float e = __expf(v);
            float ssum = e;
            for (int o = 16; o; o >>= 1) ssum += __shfl_xor_sync(0xffffffffu, ssum, o);
            if (lane == 0) red[wrp] = ssum;
            __syncthreads();
            if (tid == 0) {
                float s = 0.f;
                for (int i = 0; i < 8; i++) s += red[i];
                red[0] = s;
            }
            __syncthreads();
            float w = e * __fdividef(1.0f, red[0]);
            sw[tid] = w;
            if (q == 0) out_attn[((size_t)b * LL + t) * SS + tid] = w;
            __syncthreads();
            int e0 = q * 256 + tid;
            const float* ep = enc + ((size_t)b * SS) * EE + e0;
            float a0 = 0.f, a1 = 0.f, a2 = 0.f, a3 = 0.f;
            for (int s = 0; s < SS; s += 4) {
                a0 += sw[s + 0] * ep[(size_t)(s + 0) * EE];
                a1 += sw[s + 1] * ep[(size_t)(s + 1) * EE];
                a2 += sw[s + 2] * ep[(size_t)(s + 2) * EE];
                a3 += sw[s + 3] * ep[(size_t)(s + 3) * EE];
            }
            g_ctx[b * HH + e0] = (a0 + a1) + (a2 + a3);
            __syncthreads();
        }
        gridbar();

        // ---- P3+P4 (64 blocks): resident-weight 24-col GEMM, gate in regs --
        {
            const int i0 = blk * 8;
            const int m = tid & 31, g = tid >> 5;   // m=b, g=local i
            float ar = 0.f, az = 0.f, an = 0.f;
            for (int kt = 0; kt < 512; kt += 64) {
                const float* ap = g_ctx + (size_t)m * 512 + kt + g * 8;
                float4 a0 = *reinterpret_cast<const float4*>(ap);
                float4 a1 = *reinterpret_cast<const float4*>(ap + 4);
                As[g * 8 + 0][m] = a0.x; As[g * 8 + 1][m] = a0.y;
                As[g * 8 + 2][m] = a0.z; As[g * 8 + 3][m] = a0.w;
                As[g * 8 + 4][m] = a1.x; As[g * 8 + 5][m] = a1.y;
                As[g * 8 + 6][m] = a1.z; As[g * 8 + 7][m] = a1.w;
                __syncthreads();
                const float* wrow = sW3 + (size_t)kt * 24;
#pragma unroll
                for (int kk = 0; kk < 64; kk++) {
                    float a = As[kk][m];
                    ar = fmaf(a, wrow[kk * 24 + g], ar);
                    az = fmaf(a, wrow[kk * 24 + 8 + g], az);
                    an = fmaf(a, wrow[kk * 24 + 16 + g], an);
                }
                __syncthreads();
            }
            int b = m, i = i0 + g;
            const float* gp = g_gipre + ((size_t)t * BB + b) * G3;
            float gir = gp[i]          + ar;
            float giz = gp[HH + i]     + az;
            float gin = gp[2 * HH + i] + an;
            float ghr = g_qgh[b * 2048 + 512 + i];
            float ghz = g_qgh[b * 2048 + 1024 + i];
            float ghn = g_qgh[b * 2048 + 1536 + i];
            float r = fsig(gir + ghr);
            float z = fsig(giz + ghz);
            float n = ftanh(gin + r * ghn);
            float h = g_h[b * HH + i];
            float hn = (1.f - z) * n + z * h;
            g_h[b * HH + i] = hn;
            g_hall[(size_t)t * BB * HH + b * HH + i] = hn;
        }
        gridbar();
    }
}

// ---------------- fused log_softmax ----------------------------------------
__global__ void __launch_bounds__(256)
lsm_fused(float* __restrict__ lg) {
    extern __shared__ float srow[];
    __shared__ float red[8];
    const int row = blockIdx.x;
    const int tid = threadIdx.x;
    const int lane = tid & 31, wrp = tid >> 5;
    float* r = lg + (size_t)row * VV;

    float m = -1e30f;
    for (int v4 = tid; v4 < VV / 4; v4 += 256) {
        float4 v = reinterpret_cast<const float4*>(r)[v4];
        reinterpret_cast<float4*>(srow)[v4] = v;
        m = fmaxf(m, fmaxf(fmaxf(v.x, v.y), fmaxf(v.z, v.w)));
    }
    for (int o = 16; o; o >>= 1) m = fmaxf(m, __shfl_xor_sync(0xffffffffu, m, o));
    if (lane == 0) red[wrp] = m;
    __syncthreads();
    if (tid == 0) {
        float mm = red[0];
        for (int i = 1; i < 8; i++) mm = fmaxf(mm, red[i]);
        red[0] = mm;
    }
    __syncthreads();
    float gm = red[0];
    __syncthreads();

    float s = 0.f;
    for (int v = tid; v < VV; v += 256) s += __expf(srow[v] - gm);
    for (int o = 16; o; o >>= 1) s += __shfl_xor_sync(0xffffffffu, s, o);
    if (lane == 0) red[wrp] = s;
    __syncthreads();
    if (tid == 0) {
        float ss = 0.f;
        for (int i = 0; i < 8; i++) ss += red[i];
        red[0] = ss;
    }
    __syncthreads();
    float lse = gm + __logf(red[0]);

    for (int v4 = tid; v4 < VV / 4; v4 += 256) {
        float4 v = reinterpret_cast<const float4*>(srow)[v4];
        v.x -= lse; v.y -= lse; v.z -= lse; v.w -= lse;
        reinterpret_cast<float4*>(r)[v4] = v;
    }
}

__global__ void copy_h(float* __restrict__ out_h) {
    int i = blockIdx.x * blockDim.x + threadIdx.x;
    out_h[i] = g_h[i];
}

// --------------------------------------------------------------------------
extern "C" void kernel_launch(void* const* d_in, const int* in_sizes, int n_in,
                              void* d_out, int out_size) {
    const float* enc   = (const float*)d_in[0];
    const float* ehid  = (const float*)d_in[1];
    const int*   tgt   = (const int*)d_in[2];
    const float* W_ht  = (const float*)d_in[3];
    const float* b_ht  = (const float*)d_in[4];
    const float* emb   = (const float*)d_in[5];
    const float* Wa    = (const float*)d_in[6];
    const float* ba    = (const float*)d_in[7];
    const float* Ua    = (const float*)d_in[8];
    const float* bUa   = (const float*)d_in[9];
    const float* Va    = (const float*)d_in[10];
    const float* bVa   = (const float*)d_in[11];
    const float* W_ih  = (const float*)d_in[12];
    const float* W_hh  = (const float*)d_in[13];
    const float* b_ih  = (const float*)d_in[14];
    const float* b_hh  = (const float*)d_in[15];
    const float* W_out = (const float*)d_in[16];
    const float* b_out = (const float*)d_in[17];

    float* out    = (float*)d_out;
    float* out_lp = out;
    float* out_h  = out + (size_t)BB * LL * VV;
    float* out_at = out_h + (size_t)BB * HH;

    cudaFuncSetAttribute(lsm_fused, cudaFuncAttributeMaxDynamicSharedMemorySize, LSM_SMEM);
    cudaFuncSetAttribute(recur, cudaFuncAttributeMaxDynamicSharedMemorySize, RECUR_SMEM);

    void* p;
    cudaGetSymbolAddress(&p, g_hall);   float* p_ha = (float*)p;
    cudaGetSymbolAddress(&p, g_Uk);     float* p_Uk = (float*)p;
    cudaGetSymbolAddress(&p, g_gipre);  float* p_gp = (float*)p;
    cudaGetSymbolAddress(&p, g_haA);    __nv_bfloat16* p_haA  = (__nv_bfloat16*)p;
    cudaGetSymbolAddress(&p, g_WoutB);  __nv_bfloat16* p_WoutB = (__nv_bfloat16*)p;

    gather_emb<<<1024, 256>>>(tgt, emb);                                    // 0
    convcat4x<<<6152, 256>>>(enc, Ua, W_ih, ehid, W_ht, b_ht);              // 1
    mmaPre<<<448, 256>>>(bUa, b_ih, p_Uk, p_gp);                            // 2
    recur<<<NB, 256, RECUR_SMEM>>>(enc, Wa, ba, W_hh, b_hh, W_ih, Va, bVa, out_at); // 3

    convcat<<<(VV * 128) / 256, 256>>>(W_out, HH, p_WoutB, VV);
    convcat<<<(MALL * 128) / 256, 256>>>(p_ha, HH, p_haA, MALL);
    mmaGemm<<<dim3(MALL / 128, VV / 128), 256>>>(p_haA, p_WoutB, b_out, out_lp, VV, 1);

    lsm_fused<<<MALL, 256, LSM_SMEM>>>(out_lp);
    copy_h<<<(BB * HH) / 256, 256>>>(out_h);
}

// round 17
// speedup vs baseline: 1.2011x; 1.2011x over previous
#include <cuda_runtime.h>
#include <cuda_bf16.h>
#include <cstdint>
#include <math.h>

#define BB 32
#define SS 256
#define HH 512
#define EE 512
#define VV 32000
#define LL 64
#define SOS_TOK 1
#define G3 1536
#define MALL (LL * BB)          // 2048
#define NB 128                  // persistent blocks
#define KC 1536                 // logical split K (3*512)
#define LDK 1024                // stored row width [hi|lo]
#define LSM_SMEM (VV * 4)       // 128000 bytes

// ---------------- scratch (device globals) --------------------------------
__device__ float g_h[BB * HH];
__device__ float g_hall[MALL * HH];          // (t,b,H)
__device__ float g_Uk[BB * SS * HH];         // 16.8MB
__device__ float g_emball[MALL * HH];        // embedded tokens (t,b,H)
__device__ float g_gipre[MALL * G3];         // emb part of gi + b_ih
__device__ float g_qgh[BB * 2048];           // per-step [q | gh]
__device__ float g_scores[BB * SS];
__device__ float g_ctx[BB * HH];
__device__ unsigned int g_barcnt = 0;
__device__ unsigned int g_bargen = 0;

// split bf16 operands, stored [hi | lo], row width LDK=1024
__device__ __nv_bfloat16 g_encA[BB * SS * LDK];
__device__ __nv_bfloat16 g_UaB[HH * LDK];
__device__ __nv_bfloat16 g_embA[MALL * LDK];
__device__ __nv_bfloat16 g_WihB[G3 * LDK];
__device__ __nv_bfloat16 g_haA[MALL * LDK];
__device__ __nv_bfloat16 g_WoutB[(size_t)VV * LDK];   // 65.5MB — L2-resident

// ---------------- math helpers --------------------------------------------
__device__ __forceinline__ float ftanh_fast(float x) {
    float r;
    asm("tanh.approx.f32 %0, %1;" : "=f"(r) : "f"(x));
    return r;
}
__device__ __forceinline__ float ftanh(float x) {
    float e = __expf(2.0f * x);
    return 1.0f - __fdividef(2.0f, e + 1.0f);
}
__device__ __forceinline__ float fsig(float x) {
    return __fdividef(1.0f, 1.0f + __expf(-x));
}

__device__ __forceinline__ uint32_t smem_u32(const void* p) {
    uint32_t a;
    asm("{ .reg .u64 t; cvta.to.shared.u64 t, %1; cvt.u32.u64 %0, t; }" : "=r"(a) : "l"(p));
    return a;
}
__device__ __forceinline__ void ldsm4(uint32_t (&r)[4], uint32_t addr) {
    asm volatile("ldmatrix.sync.aligned.m8n8.x4.shared.b16 {%0,%1,%2,%3}, [%4];"
                 : "=r"(r[0]), "=r"(r[1]), "=r"(r[2]), "=r"(r[3]) : "r"(addr));
}
__device__ __forceinline__ void mma16816(float (&d)[4], const uint32_t (&a)[4],
                                         const uint32_t* b) {
    asm volatile(
        "mma.sync.aligned.m16n8k16.row.col.f32.bf16.bf16.f32 "
        "{%0,%1,%2,%3}, {%4,%5,%6,%7}, {%8,%9}, {%0,%1,%2,%3};"
        : "+f"(d[0]), "+f"(d[1]), "+f"(d[2]), "+f"(d[3])
        : "r"(a[0]), "r"(a[1]), "r"(a[2]), "r"(a[3]), "r"(b[0]), "r"(b[1]));
}
#define CP16(dst, src) \
    asm volatile("cp.async.cg.shared.global [%0], [%1], 16;" :: "r"(dst), "l"(src))
#define CPCOMMIT() asm volatile("cp.async.commit_group;" ::: "memory")
#define CPWAIT1() asm volatile("cp.async.wait_group 1;" ::: "memory")
#define CPWAIT0() asm volatile("cp.async.wait_group 0;" ::: "memory")

// ================= split conversion: fp32 -> [hi|lo] =======================
__device__ __forceinline__ uint32_t pkbf(__nv_bfloat16 a, __nv_bfloat16 b) {
    return (uint32_t)__bfloat16_as_ushort(a) | ((uint32_t)__bfloat16_as_ushort(b) << 16);
}
__device__ __forceinline__ void conv_body(const float* __restrict__ src, int srcLd,
                                          __nv_bfloat16* __restrict__ dst, int i) {
    int r = i >> 7, c4 = (i & 127) * 4;
    float4 v = *reinterpret_cast<const float4*>(src + (size_t)r * srcLd + c4);
    __nv_bfloat16 h0 = __float2bfloat16(v.x), h1 = __float2bfloat16(v.y);
    __nv_bfloat16 h2 = __float2bfloat16(v.z), h3 = __float2bfloat16(v.w);
    __nv_bfloat16 l0 = __float2bfloat16(v.x - __bfloat162float(h0));
    __nv_bfloat16 l1 = __float2bfloat16(v.y - __bfloat162float(h1));
    __nv_bfloat16 l2 = __float2bfloat16(v.z - __bfloat162float(h2));
    __nv_bfloat16 l3 = __float2bfloat16(v.w - __bfloat162float(h3));
    uint2 hw = make_uint2(pkbf(h0, h1), pkbf(h2, h3));
    uint2 lw = make_uint2(pkbf(l0, l1), pkbf(l2, l3));
    __nv_bfloat16* drow = dst + (size_t)r * LDK;
    *reinterpret_cast<uint2*>(drow + c4) = hw;
    *reinterpret_cast<uint2*>(drow + 512 + c4) = lw;
}
__global__ void __launch_bounds__(256)
convcat(const float* __restrict__ src, int srcLd,
        __nv_bfloat16* __restrict__ dst, int R) {
    int i = blockIdx.x * 256 + threadIdx.x;
    if (i >= R * 128) return;
    conv_body(src, srcLd, dst, i);
}
// fused pre-recur conversions: enc, Ua, emb_all, W_ih
__global__ void __launch_bounds__(256)
convcat4(const float* __restrict__ enc, const float* __restrict__ Ua,
         const float* __restrict__ Wih) {
    int bx = blockIdx.x;
    if (bx < 4096) {
        conv_body(enc, EE, g_encA, bx * 256 + threadIdx.x);
    } else if (bx < 4352) {
        conv_body(Ua, EE, g_UaB, (bx - 4096) * 256 + threadIdx.x);
    } else if (bx < 5376) {
        conv_body(g_emball, HH, g_embA, (bx - 4352) * 256 + threadIdx.x);
    } else {
        conv_body(Wih, 1024, g_WihB, (bx - 5376) * 256 + threadIdx.x);
    }
}

// ================= HMMA GEMM with cp.async, dedup-remapped K ===============
// Logical C = Acat(M,1536) @ Bcat(N,1536)^T with A=[hi|lo|hi], B=[hi|hi|lo];
// storage is [hi|lo] (LDK=1024): ktA = kt<1024?kt:kt-1024; ktB = kt<512?kt:kt-512.
__global__ void __launch_bounds__(256, 2)
mmaGemm(const __nv_bfloat16* __restrict__ A, const __nv_bfloat16* __restrict__ B,
        const float* __restrict__ bias, float* __restrict__ C, int ldC, int remap) {
    __shared__ __align__(16) __nv_bfloat16 sA[2][128][40];
    __shared__ __align__(16) __nv_bfloat16 sB[2][128][40];
    const int tid = threadIdx.x;
    const int lane = tid & 31, wid = tid >> 5;
    const int warpM = wid >> 1, warpN = wid & 1;
    const int m0 = blockIdx.x * 128, n0 = blockIdx.y * 128;

    float acc[2][8][4];
#pragma unroll
    for (int i = 0; i < 2; i++)
#pragma unroll
        for (int j = 0; j < 8; j++)
#pragma unroll
            for (int k = 0; k < 4; k++) acc[i][j][k] = 0.f;

    const int ldRow = tid >> 2;
    const int ldSeg = (tid & 3) * 8;

    const __nv_bfloat16* gA0 = A + (size_t)(m0 + ldRow) * LDK + ldSeg;
    const __nv_bfloat16* gA1 = gA0 + (size_t)64 * LDK;
    const __nv_bfloat16* gB0 = B + (size_t)(n0 + ldRow) * LDK + ldSeg;
    const __nv_bfloat16* gB1 = gB0 + (size_t)64 * LDK;
    uint32_t dA[2][2], dB[2][2];
#pragma unroll
    for (int st = 0; st < 2; st++) {
        dA[st][0] = smem_u32(&sA[st][ldRow][ldSeg]);
        dA[st][1] = smem_u32(&sA[st][ldRow + 64][ldSeg]);
        dB[st][0] = smem_u32(&sB[st][ldRow][ldSeg]);
        dB[st][1] = smem_u32(&sB[st][ldRow + 64][ldSeg]);
    }

    const int aRowOff = ((lane & 8) ? 8 : 0) + (lane & 7);
    const int aColOff = (lane & 16) ? 8 : 0;
    const int bRowOff = ((lane & 16) ? 8 : 0) + (lane & 7);
    const int bColOff = (lane & 8) ? 8 : 0;

    const int NK = KC / 32;   // 48

    CP16(dA[0][0], gA0); CP16(dA[0][1], gA1);
    CP16(dB[0][0], gB0); CP16(dB[0][1], gB1);
    CPCOMMIT();

    for (int it = 0; it < NK; it++) {
        if (it + 1 < NK) {
            int st = (it + 1) & 1, kt = (it + 1) * 32;
            int ktA = (kt < 1024) ? kt : kt - 1024;
            int ktB = (kt < 512) ? kt : kt - 512;
            CP16(dA[st][0], gA0 + ktA); CP16(dA[st][1], gA1 + ktA);
            CP16(dB[st][0], gB0 + ktB); CP16(dB[st][1], gB1 + ktB);
            CPCOMMIT();
            CPWAIT1();
        } else {
            CPWAIT0();
        }
        __syncthreads();

        const int cs = it & 1;
        const uint32_t aBase = smem_u32(&sA[cs][0][0]);
        const uint32_t bBase = smem_u32(&sB[cs][0][0]);
#pragma unroll
        for (int ks = 0; ks < 2; ks++) {
            const int k0 = ks * 16;
            uint32_t a[2][4];
#pragma unroll
            for (int mi = 0; mi < 2; mi++) {
                int row = warpM * 32 + mi * 16 + aRowOff;
                int col = k0 + aColOff;
                ldsm4(a[mi], aBase + (uint32_t)(row * 80 + col * 2));
            }
            uint32_t b[4][4];
#pragma unroll
            for (int bi = 0; bi < 4; bi++) {
                int row = warpN * 64 + bi * 16 + bRowOff;
                int col = k0 + bColOff;
                ldsm4(b[bi], bBase + (uint32_t)(row * 80 + col * 2));
            }
#pragma unroll
            for (int mi = 0; mi < 2; mi++)
#pragma unroll
                for (int ni = 0; ni < 8; ni++)
                    mma16816(acc[mi][ni], a[mi], &b[ni >> 1][(ni & 1) * 2]);
        }
        __syncthreads();
    }

    const int er = lane >> 2, ec = (lane & 3) * 2;
#pragma unroll
    for (int mi = 0; mi < 2; mi++) {
#pragma unroll
        for (int half = 0; half < 2; half++) {
            int m = m0 + warpM * 32 + mi * 16 + er + half * 8;
            int row = remap ? ((m & 31) * LL + (m >> 5)) : m;
            float* cp = C + (size_t)row * ldC;
#pragma unroll
            for (int ni = 0; ni < 8; ni++) {
                int n = n0 + warpN * 64 + ni * 8 + ec;
                float2 v;
                v.x = acc[mi][ni][half * 2 + 0] + bias[n];
                v.y = acc[mi][ni][half * 2 + 1] + bias[n + 1];
                *reinterpret_cast<float2*>(cp + n) = v;
            }
        }
    }
}

// ================= small GEMM (M=32) for h0 ================================
__global__ void __launch_bounds__(128)
gemm32(const float* __restrict__ A, const float* __restrict__ Bw,
       const float* __restrict__ bias, float* __restrict__ C, int N, int ld) {
    __shared__ float As[32][33];
    __shared__ float Bs[32][65];
    const int tid = threadIdx.x;
    const int n0 = blockIdx.x * 64;
    const int la_m = tid >> 2, la_k = (tid & 3) << 2;
    const int lb_n = tid >> 1, lb_k = (tid & 1) << 2;
    const int tm = tid >> 4, tn = tid & 15;

    float acc[4][4];
#pragma unroll
    for (int i = 0; i < 4; i++)
#pragma unroll
        for (int j = 0; j < 4; j++) acc[i][j] = 0.f;

    const float* Arow = A + (size_t)la_m * ld;
    const float* Brow = Bw + (size_t)(n0 + lb_n) * ld;

    for (int k0 = 0; k0 < ld; k0 += 32) {
        float4 av0 = *reinterpret_cast<const float4*>(Arow + k0 + la_k);
        float4 av1 = *reinterpret_cast<const float4*>(Arow + k0 + la_k + 16);
        As[la_k + 0][la_m] = av0.x;  As[la_k + 1][la_m] = av0.y;
        As[la_k + 2][la_m] = av0.z;  As[la_k + 3][la_m] = av0.w;
        As[la_k + 16][la_m] = av1.x; As[la_k + 17][la_m] = av1.y;
        As[la_k + 18][la_m] = av1.z; As[la_k + 19][la_m] = av1.w;
        float4 bv0 = *reinterpret_cast<const float4*>(Brow + k0 + lb_k);
        float4 bv1 = *reinterpret_cast<const float4*>(Brow + k0 + lb_k + 8);
        float4 bv2 = *reinterpret_cast<const float4*>(Brow + k0 + lb_k + 16);
        float4 bv3 = *reinterpret_cast<const float4*>(Brow + k0 + lb_k + 24);
        Bs[lb_k + 0][lb_n] = bv0.x;  Bs[lb_k + 1][lb_n] = bv0.y;
        Bs[lb_k + 2][lb_n] = bv0.z;  Bs[lb_k + 3][lb_n] = bv0.w;
        Bs[lb_k + 8][lb_n] = bv1.x;  Bs[lb_k + 9][lb_n] = bv1.y;
        Bs[lb_k + 10][lb_n] = bv1.z; Bs[lb_k + 11][lb_n] = bv1.w;
        Bs[lb_k + 16][lb_n] = bv2.x; Bs[lb_k + 17][lb_n] = bv2.y;
        Bs[lb_k + 18][lb_n] = bv2.z; Bs[lb_k + 19][lb_n] = bv2.w;
        Bs[lb_k + 24][lb_n] = bv3.x; Bs[lb_k + 25][lb_n] = bv3.y;
        Bs[lb_k + 26][lb_n] = bv3.z; Bs[lb_k + 27][lb_n] = bv3.w;
        __syncthreads();
#pragma unroll
        for (int kk = 0; kk < 32; kk++) {
            float a0 = As[kk][tm * 4 + 0], a1 = As[kk][tm * 4 + 1];
            float a2 = As[kk][tm * 4 + 2], a3 = As[kk][tm * 4 + 3];
            float b0 = Bs[kk][tn * 4 + 0], b1 = Bs[kk][tn * 4 + 1];
            float b2 = Bs[kk][tn * 4 + 2], b3 = Bs[kk][tn * 4 + 3];
            acc[0][0] += a0 * b0; acc[0][1] += a0 * b1; acc[0][2] += a0 * b2; acc[0][3] += a0 * b3;
            acc[1][0] += a1 * b0; acc[1][1] += a1 * b1; acc[1][2] += a1 * b2; acc[1][3] += a1 * b3;
            acc[2][0] += a2 * b0; acc[2][1] += a2 * b1; acc[2][2] += a2 * b2; acc[2][3] += a2 * b3;
            acc[3][0] += a3 * b0; acc[3][1] += a3 * b1; acc[3][2] += a3 * b2; acc[3][3] += a3 * b3;
        }
        __syncthreads();
    }
#pragma unroll
    for (int i = 0; i < 4; i++) {
        float* crow = C + (size_t)(tm * 4 + i) * N + n0 + tn * 4;
#pragma unroll
        for (int j = 0; j < 4; j++) crow[j] = acc[i][j] + bias[n0 + tn * 4 + j];
    }
}

// ================= embedding gather ========================================
__global__ void gather_emb(const int* __restrict__ tgt, const float* __restrict__ emb) {
    int i = blockIdx.x * 256 + threadIdx.x;
    int row = i >> 7;
    int c = i & 127;
    int tcur = row >> 5, b = row & 31;
    int tok = (tcur == 0) ? SOS_TOK : tgt[b * LL + tcur - 1];
    reinterpret_cast<float4*>(g_emball)[(size_t)row * 128 + c] =
        reinterpret_cast<const float4*>(emb + (size_t)tok * HH)[c];
}

// ================= persistent recurrence kernel (R13 champion) =============
__device__ __forceinline__ void gridbar() {
    __syncthreads();
    if (threadIdx.x == 0) {
        volatile unsigned int* genp = &g_bargen;
        unsigned int gen = *genp;
        __threadfence();
        unsigned int t = atomicAdd(&g_barcnt, 1u);
        if (t == NB - 1) {
            g_barcnt = 0;
            __threadfence();
            *genp = gen + 1;
        } else {
            while (*genp == gen) { }
        }
        __threadfence();
    }
    __syncthreads();
}

__device__ __forceinline__ void mgemm16(
    float* __restrict__ sm,
    const float* __restrict__ A,
    const float* __restrict__ Brow0, int ldB,
    const float* __restrict__ bias,
    float* __restrict__ C, int ldC) {
    float (*As)[33] = reinterpret_cast<float(*)[33]>(sm);
    float (*Bs)[18] = reinterpret_cast<float(*)[18]>(sm + 64 * 33);
    const int tid = threadIdx.x;
    const int m = tid & 31, g = tid >> 5;
    const int br = tid & 15, bg = tid >> 4;
    float acc0 = 0.f, acc1 = 0.f;
    for (int kt = 0; kt < 512; kt += 64) {
        const float* ap = A + (size_t)m * 512 + kt + g * 8;
        float4 a0 = *reinterpret_cast<const float4*>(ap);
        float4 a1 = *reinterpret_cast<const float4*>(ap + 4);
        As[g * 8 + 0][m] = a0.x; As[g * 8 + 1][m] = a0.y;
        As[g * 8 + 2][m] = a0.z; As[g * 8 + 3][m] = a0.w;
        As[g * 8 + 4][m] = a1.x; As[g * 8 + 5][m] = a1.y;
        As[g * 8 + 6][m] = a1.z; As[g * 8 + 7][m] = a1.w;
        float4 bv = *reinterpret_cast<const float4*>(Brow0 + (size_t)br * ldB + kt + bg * 4);
        Bs[bg * 4 + 0][br] = bv.x; Bs[bg * 4 + 1][br] = bv.y;
        Bs[bg * 4 + 2][br] = bv.z; Bs[bg * 4 + 3][br] = bv.w;
        __syncthreads();
#pragma unroll
        for (int kk = 0; kk < 64; kk++) {
            float a = As[kk][m];
            float2 bb = *reinterpret_cast<const float2*>(&Bs[kk][g * 2]);
            acc0 = fmaf(a, bb.x, acc0);
            acc1 = fmaf(a, bb.y, acc1);
        }
        __syncthreads();
    }
    int j = g * 2;
    float b0 = bias ? bias[j] : 0.f;
    float b1 = bias ? bias[j + 1] : 0.f;
    C[(size_t)m * ldC + j] = acc0 + b0;
    C[(size_t)m * ldC + j + 1] = acc1 + b1;
}

#define RSM_TOTAL (64 * 33 + 48 * 68 + 32 * 48)

__global__ void __launch_bounds__(256)
recur(const float* __restrict__ enc,
      const float* __restrict__ Wa, const float* __restrict__ ba,
      const float* __restrict__ W_hh, const float* __restrict__ b_hh,
      const float* __restrict__ W_ih,
      const float* __restrict__ Va, const float* __restrict__ bVa,
      float* __restrict__ out_attn) {
    __shared__ float sm[RSM_TOTAL];
    const int blk = blockIdx.x;
    const int tid = threadIdx.x;
    const int lane = tid & 31;
    const int wrp = tid >> 5;

    for (int t = 0; t < LL; t++) {
        // P1: [q | gh] = h @ [Wa; W_hh]^T + [ba; b_hh]
        {
            int n0 = blk * 16;
            const float* Bp; const float* bp; int brow;
            if (n0 < HH) { Bp = Wa; bp = ba; brow = n0; }
            else         { Bp = W_hh; bp = b_hh; brow = n0 - HH; }
            mgemm16(sm, g_h, Bp + (size_t)brow * HH, HH, bp + brow,
                    g_qgh + n0, 2048);
        }
        gridbar();

        // P2a: scores (tanh.approx)
        {
            int b = blk & 31;
            int s0 = (blk >> 5) * 64;
            float* sq = sm;
            float* sva = sm + 512;
            sq[tid] = g_qgh[b * 2048 + tid];
            sq[tid + 256] = g_qgh[b * 2048 + tid + 256];
            sva[tid] = Va[tid];
            sva[tid + 256] = Va[tid + 256];
            __syncthreads();
            const float4* q4 = reinterpret_cast<const float4*>(sq);
            const float4* v4 = reinterpret_cast<const float4*>(sva);
            for (int it = 0; it < 8; it++) {
                int s = s0 + wrp + 8 * it;
                const float4* u4 = reinterpret_cast<const float4*>(
                    g_Uk + ((size_t)(b * SS + s)) * HH);
                float p = 0.f;
#pragma unroll
                for (int c = 0; c < 4; c++) {
                    int k4 = lane + 32 * c;
                    float4 uv = u4[k4];
                    float4 qv = q4[k4];
                    float4 vv = v4[k4];
                    p += vv.x * ftanh_fast(qv.x + uv.x) + vv.y * ftanh_fast(qv.y + uv.y)
                       + vv.z * ftanh_fast(qv.z + uv.z) + vv.w * ftanh_fast(qv.w + uv.w);
                }
                for (int o = 16; o; o >>= 1) p += __shfl_xor_sync(0xffffffffu, p, o);
                if (lane == 0) g_scores[b * SS + s] = p + bVa[0];
            }
            __syncthreads();
        }
        gridbar();

        // P2b: softmax (no max-sub: scores bounded) + attn out + ctx
        {
            int b = blk >> 2, q = blk & 3;
            float* sw = sm;
            float* red = sm + 256;
            float* part = sm + 264;
            float v = g_scores[b * SS + tid];
            float e = __expf(v);
            float ssum = e;
            for (int o = 16; o; o >>= 1) ssum += __shfl_xor_sync(0xffffffffu, ssum, o);
            if (lane == 0) red[wrp] = ssum;
            __syncthreads();
            if (tid == 0) {
                float s = 0.f;
                for (int i = 0; i < 8; i++) s += red[i];
                red[0] = s;
            }
            __syncthreads();
            float w = e * __fdividef(1.0f, red[0]);
            sw[tid] = w;
            if (q == 0) out_attn[((size_t)b * LL + t) * SS + tid] = w;
            __syncthreads();
            int e0 = q * 128 + (tid & 127);
            int shalf = tid >> 7;
            const float* ep = enc + ((size_t)b * SS + shalf * 128) * EE + e0;
            const float* swp = sw + shalf * 128;
            float a0 = 0.f, a1 = 0.f, a2 = 0.f, a3 = 0.f;
            for (int s = 0; s < 128; s += 4) {
                a0 += swp[s + 0] * ep[(size_t)(s + 0) * EE];
                a1 += swp[s + 1] * ep[(size_t)(s + 1) * EE];
                a2 += swp[s + 2] * ep[(size_t)(s + 2) * EE];
                a3 += swp[s + 3] * ep[(size_t)(s + 3) * EE];
            }
            part[tid] = (a0 + a1) + (a2 + a3);
            __syncthreads();
            if (tid < 128) g_ctx[b * HH + e0] = part[tid] + part[tid + 128];
            __syncthreads();
        }
        gridbar();

        // P3+P4 fused (32 blocks): one 48-col GEMM (r,z,n slices) + gate
        if (blk < 32) {
            float (*As)[33] = reinterpret_cast<float(*)[33]>(sm);
            float (*Bs)[68] = reinterpret_cast<float(*)[68]>(sm + 64 * 33);
            float* sc = sm + 64 * 33 + 48 * 68;
            const int i0 = blk * 16;
            const int m = tid & 31, g = tid >> 5;
            float acc[6];
#pragma unroll
            for (int c = 0; c < 6; c++) acc[c] = 0.f;

            for (int kt = 0; kt < 512; kt += 64) {
                const float* ap = g_ctx + (size_t)m * 512 + kt + g * 8;
                float4 a0 = *reinterpret_cast<const float4*>(ap);
                float4 a1 = *reinterpret_cast<const float4*>(ap + 4);
                As[g * 8 + 0][m] = a0.x; As[g * 8 + 1][m] = a0.y;
                As[g * 8 + 2][m] = a0.z; As[g * 8 + 3][m] = a0.w;
                As[g * 8 + 4][m] = a1.x; As[g * 8 + 5][m] = a1.y;
                As[g * 8 + 6][m] = a1.z; As[g * 8 + 7][m] = a1.w;
#pragma unroll
                for (int r3 = 0; r3 < 3; r3++) {
                    int e = tid + 256 * r3;
                    int j = e >> 4;
                    int k4 = (e & 15) * 4;
                    int row = (j >> 4) * 512 + i0 + (j & 15);
                    float4 bv = *reinterpret_cast<const float4*>(
                        W_ih + (size_t)row * 1024 + 512 + kt + k4);
                    *reinterpret_cast<float4*>(&Bs[j][k4]) = bv;
                }
                __syncthreads();
#pragma unroll
                for (int kk = 0; kk < 64; kk++) {
                    float a = As[kk][m];
                    acc[0] = fmaf(a, Bs[g * 6 + 0][kk], acc[0]);
                    acc[1] = fmaf(a, Bs[g * 6 + 1][kk], acc[1]);
                    acc[2] = fmaf(a, Bs[g * 6 + 2][kk], acc[2]);
                    acc[3] = fmaf(a, Bs[g * 6 + 3][kk], acc[3]);
                    acc[4] = fmaf(a, Bs[g * 6 + 4][kk], acc[4]);
                    acc[5] = fmaf(a, Bs[g * 6 + 5][kk], acc[5]);
                }
                __syncthreads();
            }
#pragma unroll
            for (int c = 0; c < 6; c++) sc[m * 48 + g * 6 + c] = acc[c];
            __syncthreads();

#pragma unroll
            for (int u = 0; u < 2; u++) {
                int idx = tid + 256 * u;
                int b = idx >> 4, c = idx & 15;
                int i = i0 + c;
                const float* gp = g_gipre + ((size_t)t * BB + b) * G3;
                float gir = gp[i]          + sc[b * 48 + c];
                float giz = gp[HH + i]     + sc[b * 48 + 16 + c];
                float gin = gp[2 * HH + i] + sc[b * 48 + 32 + c];
                float ghr = g_qgh[b * 2048 + 512 + i];
                float ghz = g_qgh[b * 2048 + 1024 + i];
                float ghn = g_qgh[b * 2048 + 1536 + i];
                float r = fsig(gir + ghr);
                float z = fsig(giz + ghz);
                float n = ftanh(gin + r * ghn);
                float h = g_h[b * HH + i];
                float hn = (1.f - z) * n + z * h;
                g_h[b * HH + i] = hn;
                g_hall[(size_t)t * BB * HH + b * HH + i] = hn;
            }
        }
        gridbar();
    }
}

// ---------------- fused log_softmax ----------------------------------------
__global__ void __launch_bounds__(256)
lsm_fused(float* __restrict__ lg) {
    extern __shared__ float srow[];
    __shared__ float red[8];
    const int row = blockIdx.x;
    const int tid = threadIdx.x;
    const int lane = tid & 31, wrp = tid >> 5;
    float* r = lg + (size_t)row * VV;

    float m = -1e30f;
    for (int v4 = tid; v4 < VV / 4; v4 += 256) {
        float4 v = reinterpret_cast<const float4*>(r)[v4];
        reinterpret_cast<float4*>(srow)[v4] = v;
        m = fmaxf(m, fmaxf(fmaxf(v.x, v.y), fmaxf(v.z, v.w)));
    }
    for (int o = 16; o; o >>= 1) m = fmaxf(m, __shfl_xor_sync(0xffffffffu, m, o));
    if (lane == 0) red[wrp] = m;
    __syncthreads();
    if (tid == 0) {
        float mm = red[0];
        for (int i = 1; i < 8; i++) mm = fmaxf(mm, red[i]);
        red[0] = mm;
    }
    __syncthreads();
    float gm = red[0];
    __syncthreads();

    float s = 0.f;
    for (int v = tid; v < VV; v += 256) s += __expf(srow[v] - gm);
    for (int o = 16; o; o >>= 1) s += __shfl_xor_sync(0xffffffffu, s, o);
    if (lane == 0) red[wrp] = s;
    __syncthreads();
    if (tid == 0) {
        float ss = 0.f;
        for (int i = 0; i < 8; i++) ss += red[i];
        red[0] = ss;
    }
    __syncthreads();
    float lse = gm + __logf(red[0]);

    for (int v4 = tid; v4 < VV / 4; v4 += 256) {
        float4 v = reinterpret_cast<const float4*>(srow)[v4];
        v.x -= lse; v.y -= lse; v.z -= lse; v.w -= lse;
        reinterpret_cast<float4*>(r)[v4] = v;
    }
}

__global__ void copy_h(float* __restrict__ out_h) {
    int i = blockIdx.x * blockDim.x + threadIdx.x;
    out_h[i] = g_h[i];
}

// --------------------------------------------------------------------------
extern "C" void kernel_launch(void* const* d_in, const int* in_sizes, int n_in,
                              void* d_out, int out_size) {
    const float* enc   = (const float*)d_in[0];
    const float* ehid  = (const float*)d_in[1];
    const int*   tgt   = (const int*)d_in[2];
    const float* W_ht  = (const float*)d_in[3];
    const float* b_ht  = (const float*)d_in[4];
    const float* emb   = (const float*)d_in[5];
    const float* Wa    = (const float*)d_in[6];
    const float* ba    = (const float*)d_in[7];
    const float* Ua    = (const float*)d_in[8];
    const float* bUa   = (const float*)d_in[9];
    const float* Va    = (const float*)d_in[10];
    const float* bVa   = (const float*)d_in[11];
    const float* W_ih  = (const float*)d_in[12];
    const float* W_hh  = (const float*)d_in[13];
    const float* b_ih  = (const float*)d_in[14];
    const float* b_hh  = (const float*)d_in[15];
    const float* W_out = (const float*)d_in[16];
    const float* b_out = (const float*)d_in[17];

    float* out    = (float*)d_out;
    float* out_lp = out;
    float* out_h  = out + (size_t)BB * LL * VV;
    float* out_at = out_h + (size_t)BB * HH;

    cudaFuncSetAttribute(lsm_fused, cudaFuncAttributeMaxDynamicSharedMemorySize, LSM_SMEM);

    void* p;
    cudaGetSymbolAddress(&p, g_h);      float* p_h  = (float*)p;
    cudaGetSymbolAddress(&p, g_hall);   float* p_ha = (float*)p;
    cudaGetSymbolAddress(&p, g_Uk);     float* p_Uk = (float*)p;
    cudaGetSymbolAddress(&p, g_gipre);  float* p_gp = (float*)p;
    cudaGetSymbolAddress(&p, g_encA);   __nv_bfloat16* p_encA = (__nv_bfloat16*)p;
    cudaGetSymbolAddress(&p, g_UaB);    __nv_bfloat16* p_UaB  = (__nv_bfloat16*)p;
    cudaGetSymbolAddress(&p, g_embA);   __nv_bfloat16* p_embA = (__nv_bfloat16*)p;
    cudaGetSymbolAddress(&p, g_WihB);   __nv_bfloat16* p_WihB = (__nv_bfloat16*)p;
    cudaGetSymbolAddress(&p, g_haA);    __nv_bfloat16* p_haA  = (__nv_bfloat16*)p;
    cudaGetSymbolAddress(&p, g_WoutB);  __nv_bfloat16* p_WoutB = (__nv_bfloat16*)p;

    gather_emb<<<1024, 256>>>(tgt, emb);
    convcat4<<<6144, 256>>>(enc, Ua, W_ih);
    gemm32<<<HH / 64, 128>>>(ehid, W_ht, b_ht, p_h, HH, EE);
    mmaGemm<<<dim3(BB * SS / 128, HH / 128), 256>>>(p_encA, p_UaB, bUa, p_Uk, HH, 0);
    mmaGemm<<<dim3(MALL / 128, G3 / 128), 256>>>(p_embA, p_WihB, b_ih, p_gp, G3, 0);

    recur<<<NB, 256>>>(enc, Wa, ba, W_hh, b_hh, W_ih, Va, bVa, out_at);

    convcat<<<(VV * 128) / 256, 256>>>(W_out, HH, p_WoutB, VV);
    convcat<<<(MALL * 128) / 256, 256>>>(p_ha, HH, p_haA, MALL);
    mmaGemm<<<dim3(MALL / 128, VV / 128), 256>>>(p_haA, p_WoutB, b_out, out_lp, VV, 1);

    lsm_fused<<<MALL, 256, LSM_SMEM>>>(out_lp);
    copy_h<<<(BB * HH) / 256, 256>>>(out_h);
}